// round 1
// baseline (speedup 1.0000x reference)
#include <cuda_runtime.h>

#define NN 50000
#define NE 800000
#define DD 128
#define KK 256

// ---------------- scratch (device globals; no allocations allowed) ----------
__device__ float g_ef1[(size_t)NE * DD];   // ef @ W_edge      (409.6 MB)
__device__ float g_s[(size_t)NN * DD];     // segment sum -> nb (25.6 MB)
__device__ float g_deg[NN];

// ---------------- small utility kernels -------------------------------------
__global__ void zero_kernel() {
    int stride = gridDim.x * blockDim.x;
    int t = blockIdx.x * blockDim.x + threadIdx.x;
    for (int i = t; i < NN * DD; i += stride) g_s[i] = 0.0f;
    for (int i = t; i < NN; i += stride) g_deg[i] = 0.0f;
}

__global__ void deg_kernel(const int* __restrict__ dst) {
    int e = blockIdx.x * blockDim.x + threadIdx.x;
    if (e < NE) atomicAdd(&g_deg[dst[e]], 1.0f);
}

__global__ void nb_kernel() {
    int stride = gridDim.x * blockDim.x;
    int t = blockIdx.x * blockDim.x + threadIdx.x;
    for (int i = t; i < NN * DD; i += stride) {
        float d = g_deg[i >> 7];
        g_s[i] = g_s[i] / fmaxf(d, 1.0f);
    }
}

// ---------------- 4x4 register micro-tile FMA helper ------------------------
__device__ __forceinline__ void fma16(float acc[4][4],
                                      float a0, float a1, float a2, float a3,
                                      float4 wv) {
    acc[0][0] = fmaf(a0, wv.x, acc[0][0]);
    acc[0][1] = fmaf(a0, wv.y, acc[0][1]);
    acc[0][2] = fmaf(a0, wv.z, acc[0][2]);
    acc[0][3] = fmaf(a0, wv.w, acc[0][3]);
    acc[1][0] = fmaf(a1, wv.x, acc[1][0]);
    acc[1][1] = fmaf(a1, wv.y, acc[1][1]);
    acc[1][2] = fmaf(a1, wv.z, acc[1][2]);
    acc[1][3] = fmaf(a1, wv.w, acc[1][3]);
    acc[2][0] = fmaf(a2, wv.x, acc[2][0]);
    acc[2][1] = fmaf(a2, wv.y, acc[2][1]);
    acc[2][2] = fmaf(a2, wv.z, acc[2][2]);
    acc[2][3] = fmaf(a2, wv.w, acc[2][3]);
    acc[3][0] = fmaf(a3, wv.x, acc[3][0]);
    acc[3][1] = fmaf(a3, wv.y, acc[3][1]);
    acc[3][2] = fmaf(a3, wv.z, acc[3][2]);
    acc[3][3] = fmaf(a3, wv.w, acc[3][3]);
}

// ---------------- kernel: nf2 = relu(nf @ W_node + node_bias) ---------------
// block: 512 threads, 64 rows x 128 cols. smem: W(64KB) + A(32KB) = 96KB
__global__ __launch_bounds__(512, 1)
void node_gemm(const float* __restrict__ nf, const float* __restrict__ W,
               const float* __restrict__ bias, float* __restrict__ out) {
    extern __shared__ float sm[];
    float* sW = sm;             // [128][128] k-major
    float* sA = sm + DD * DD;   // [64][128]
    const int tid  = threadIdx.x;
    const int warp = tid >> 5, lane = tid & 31;
    const int row0 = blockIdx.x * 64;

#pragma unroll
    for (int i = 0; i < 8; i++) {
        int idx = tid + i * 512;
        ((float4*)sW)[idx] = ((const float4*)W)[idx];
    }
#pragma unroll
    for (int i = 0; i < 4; i++) {
        int idx = tid + i * 512;            // float4 index, 32 per row
        int r = idx >> 5, c = idx & 31;
        int row = row0 + r;
        float4 v = make_float4(0.f, 0.f, 0.f, 0.f);
        if (row < NN) v = ((const float4*)(nf + (size_t)row * DD))[c];
        ((float4*)sA)[idx] = v;
    }
    __syncthreads();

    float acc[4][4];
#pragma unroll
    for (int i = 0; i < 4; i++)
#pragma unroll
        for (int j = 0; j < 4; j++) acc[i][j] = 0.f;

    const int r0 = warp * 4, c0 = lane * 4;
#pragma unroll 2
    for (int k = 0; k < DD; k += 4) {
        float4 a0 = *(const float4*)(sA + (r0 + 0) * DD + k);
        float4 a1 = *(const float4*)(sA + (r0 + 1) * DD + k);
        float4 a2 = *(const float4*)(sA + (r0 + 2) * DD + k);
        float4 a3 = *(const float4*)(sA + (r0 + 3) * DD + k);
        float4 w0 = *(const float4*)(sW + (k + 0) * DD + c0);
        float4 w1 = *(const float4*)(sW + (k + 1) * DD + c0);
        float4 w2 = *(const float4*)(sW + (k + 2) * DD + c0);
        float4 w3 = *(const float4*)(sW + (k + 3) * DD + c0);
        fma16(acc, a0.x, a1.x, a2.x, a3.x, w0);
        fma16(acc, a0.y, a1.y, a2.y, a3.y, w1);
        fma16(acc, a0.z, a1.z, a2.z, a3.z, w2);
        fma16(acc, a0.w, a1.w, a2.w, a3.w, w3);
    }

    float4 bv = *(const float4*)(bias + c0);
#pragma unroll
    for (int i = 0; i < 4; i++) {
        int row = row0 + r0 + i;
        if (row < NN) {
            float4 o;
            o.x = fmaxf(acc[i][0] + bv.x, 0.f);
            o.y = fmaxf(acc[i][1] + bv.y, 0.f);
            o.z = fmaxf(acc[i][2] + bv.z, 0.f);
            o.w = fmaxf(acc[i][3] + bv.w, 0.f);
            *(float4*)(out + (size_t)row * DD + c0) = o;
        }
    }
}

// ---------------- kernel: ef1 = ef @ W_edge; scatter-add into s -------------
// NE is a multiple of 64 -> no guards.
__global__ __launch_bounds__(512, 1)
void edge_gemm(const float* __restrict__ ef, const float* __restrict__ W,
               const int* __restrict__ dst) {
    extern __shared__ float sm[];
    float* sW = sm;
    float* sA = sm + DD * DD;
    const int tid  = threadIdx.x;
    const int warp = tid >> 5, lane = tid & 31;
    const int row0 = blockIdx.x * 64;

#pragma unroll
    for (int i = 0; i < 8; i++) {
        int idx = tid + i * 512;
        ((float4*)sW)[idx] = ((const float4*)W)[idx];
    }
#pragma unroll
    for (int i = 0; i < 4; i++) {
        int idx = tid + i * 512;
        int r = idx >> 5, c = idx & 31;
        ((float4*)sA)[idx] = ((const float4*)(ef + (size_t)(row0 + r) * DD))[c];
    }
    __syncthreads();

    float acc[4][4];
#pragma unroll
    for (int i = 0; i < 4; i++)
#pragma unroll
        for (int j = 0; j < 4; j++) acc[i][j] = 0.f;

    const int r0 = warp * 4, c0 = lane * 4;
#pragma unroll 2
    for (int k = 0; k < DD; k += 4) {
        float4 a0 = *(const float4*)(sA + (r0 + 0) * DD + k);
        float4 a1 = *(const float4*)(sA + (r0 + 1) * DD + k);
        float4 a2 = *(const float4*)(sA + (r0 + 2) * DD + k);
        float4 a3 = *(const float4*)(sA + (r0 + 3) * DD + k);
        float4 w0 = *(const float4*)(sW + (k + 0) * DD + c0);
        float4 w1 = *(const float4*)(sW + (k + 1) * DD + c0);
        float4 w2 = *(const float4*)(sW + (k + 2) * DD + c0);
        float4 w3 = *(const float4*)(sW + (k + 3) * DD + c0);
        fma16(acc, a0.x, a1.x, a2.x, a3.x, w0);
        fma16(acc, a0.y, a1.y, a2.y, a3.y, w1);
        fma16(acc, a0.z, a1.z, a2.z, a3.z, w2);
        fma16(acc, a0.w, a1.w, a2.w, a3.w, w3);
    }

#pragma unroll
    for (int i = 0; i < 4; i++) {
        int e = row0 + r0 + i;
        int dn = dst[e];                      // warp-uniform -> broadcast
        float4 o = make_float4(acc[i][0], acc[i][1], acc[i][2], acc[i][3]);
        *(float4*)(g_ef1 + (size_t)e * DD + c0) = o;
        float* sp = g_s + (size_t)dn * DD + c0;
        atomicAdd(sp + 0, o.x);
        atomicAdd(sp + 1, o.y);
        atomicAdd(sp + 2, o.z);
        atomicAdd(sp + 3, o.w);
    }
}

// ---------------- kernel: ef2 = relu([ef1+nb[dst], 0.5(nf2[src]+nf2[dst])] @ dense_W + b)
// block: 512 threads, 64 edges x 128 cols, K=256.
// smem: W(128KB) + A(64KB) = 192KB -> 1 block/SM.
__global__ __launch_bounds__(512, 1)
void edge_out_gemm(const int* __restrict__ src, const int* __restrict__ dst,
                   const float* __restrict__ dW, const float* __restrict__ db,
                   const float* __restrict__ eb, const float* __restrict__ nf2,
                   float* __restrict__ out) {
    extern __shared__ float sm[];
    float* sW = sm;              // [256][128] k-major
    float* sA = sm + KK * DD;    // [64][256]
    const int tid  = threadIdx.x;
    const int warp = tid >> 5, lane = tid & 31;
    const int e0 = blockIdx.x * 64;

#pragma unroll
    for (int i = 0; i < 16; i++) {
        int idx = tid + i * 512;
        ((float4*)sW)[idx] = ((const float4*)dW)[idx];
    }
    // Build A tile: 64 edges x 256 cols = 4096 float4
#pragma unroll
    for (int i = 0; i < 8; i++) {
        int idx = tid + i * 512;
        int r = idx >> 6;          // edge within tile (64 float4 per row)
        int cc = idx & 63;         // float4 column
        int e = e0 + r;
        float4 v;
        if (cc < 32) {
            float4 a = ((const float4*)(g_ef1 + (size_t)e * DD))[cc];
            int dn = dst[e];
            float4 b = ((const float4*)(g_s + (size_t)dn * DD))[cc];
            v = make_float4(a.x + b.x, a.y + b.y, a.z + b.z, a.w + b.w);
        } else {
            int sn = src[e], dn = dst[e];
            float4 a = ((const float4*)(nf2 + (size_t)sn * DD))[cc - 32];
            float4 b = ((const float4*)(nf2 + (size_t)dn * DD))[cc - 32];
            v = make_float4(0.5f * (a.x + b.x), 0.5f * (a.y + b.y),
                            0.5f * (a.z + b.z), 0.5f * (a.w + b.w));
        }
        ((float4*)sA)[idx] = v;
    }
    __syncthreads();

    float acc[4][4];
#pragma unroll
    for (int i = 0; i < 4; i++)
#pragma unroll
        for (int j = 0; j < 4; j++) acc[i][j] = 0.f;

    const int r0 = warp * 4, c0 = lane * 4;
#pragma unroll 2
    for (int k = 0; k < KK; k += 4) {
        float4 a0 = *(const float4*)(sA + (r0 + 0) * KK + k);
        float4 a1 = *(const float4*)(sA + (r0 + 1) * KK + k);
        float4 a2 = *(const float4*)(sA + (r0 + 2) * KK + k);
        float4 a3 = *(const float4*)(sA + (r0 + 3) * KK + k);
        float4 w0 = *(const float4*)(sW + (k + 0) * DD + c0);
        float4 w1 = *(const float4*)(sW + (k + 1) * DD + c0);
        float4 w2 = *(const float4*)(sW + (k + 2) * DD + c0);
        float4 w3 = *(const float4*)(sW + (k + 3) * DD + c0);
        fma16(acc, a0.x, a1.x, a2.x, a3.x, w0);
        fma16(acc, a0.y, a1.y, a2.y, a3.y, w1);
        fma16(acc, a0.z, a1.z, a2.z, a3.z, w2);
        fma16(acc, a0.w, a1.w, a2.w, a3.w, w3);
    }

    float4 b1 = *(const float4*)(db + c0);
    float4 b2 = *(const float4*)(eb + c0);
#pragma unroll
    for (int i = 0; i < 4; i++) {
        int e = e0 + r0 + i;
        float4 o;
        o.x = fmaxf(acc[i][0] + b1.x + b2.x, 0.f);
        o.y = fmaxf(acc[i][1] + b1.y + b2.y, 0.f);
        o.z = fmaxf(acc[i][2] + b1.z + b2.z, 0.f);
        o.w = fmaxf(acc[i][3] + b1.w + b2.w, 0.f);
        *(float4*)(out + (size_t)e * DD + c0) = o;
    }
}

// ---------------- launch -----------------------------------------------------
extern "C" void kernel_launch(void* const* d_in, const int* in_sizes, int n_in,
                              void* d_out, int out_size) {
    (void)in_sizes; (void)n_in; (void)out_size;
    const float* nf        = (const float*)d_in[0];
    const float* ef        = (const float*)d_in[1];
    const float* W_node    = (const float*)d_in[2];
    const float* W_edge    = (const float*)d_in[3];
    const float* node_bias = (const float*)d_in[4];
    const float* edge_bias = (const float*)d_in[5];
    const float* dense_W   = (const float*)d_in[6];
    const float* dense_b   = (const float*)d_in[7];
    const int*   src       = (const int*)d_in[8];
    const int*   dst       = (const int*)d_in[9];

    float* nf2 = (float*)d_out;                       // [NN, DD]
    float* ef2 = (float*)d_out + (size_t)NN * DD;     // [NE, DD]

    cudaFuncSetAttribute(node_gemm, cudaFuncAttributeMaxDynamicSharedMemorySize, 96 * 1024);
    cudaFuncSetAttribute(edge_gemm, cudaFuncAttributeMaxDynamicSharedMemorySize, 96 * 1024);
    cudaFuncSetAttribute(edge_out_gemm, cudaFuncAttributeMaxDynamicSharedMemorySize, 192 * 1024);

    zero_kernel<<<1024, 256>>>();
    deg_kernel<<<(NE + 255) / 256, 256>>>(dst);
    node_gemm<<<(NN + 63) / 64, 512, 96 * 1024>>>(nf, W_node, node_bias, nf2);
    edge_gemm<<<NE / 64, 512, 96 * 1024>>>(ef, W_edge, dst);
    nb_kernel<<<1024, 256>>>();
    edge_out_gemm<<<NE / 64, 512, 192 * 1024>>>(src, dst, dense_W, dense_b,
                                                edge_bias, nf2, ef2);
}

// round 7
// speedup vs baseline: 1.7963x; 1.7963x over previous
#include <cuda_runtime.h>
#include <cuda_bf16.h>
#include <cstdint>

#define NN 50000
#define NE 800000
#define DD 128
#define KK 256

// ---------------- scratch ----------------------------------------------------
__device__ float g_ef1[(size_t)NE * DD];     // ef @ W_edge
__device__ float g_s[(size_t)NN * DD];       // segment sum -> nb
__device__ float g_deg[NN];
// split+transposed weights: B[n][k] = W[k][n], bf16 hi/lo (col-major B frags)
__device__ __nv_bfloat16 g_Bn_h[DD * DD], g_Bn_l[DD * DD];
__device__ __nv_bfloat16 g_Be_h[DD * DD], g_Be_l[DD * DD];
__device__ __nv_bfloat16 g_Bd_h[DD * KK], g_Bd_l[DD * KK];

// ---------------- smem layout (32-bit words) ----------------------------------
// 128 rows x 64 data words, padded to 68 words/row => (4g+t) bank pattern is
// conflict-free for fragment loads. Four tiles: A_hi, A_lo, B_hi, B_lo.
#define WPAD 68
#define SA_H 0
#define SA_L (128 * WPAD)
#define SB_H (2 * 128 * WPAD)
#define SB_L (3 * 128 * WPAD)
#define SMEM_WORDS (4 * 128 * WPAD)
#define SMEM_BYTES (SMEM_WORDS * 4)   // 139264

// ---------------- helpers ------------------------------------------------------
__device__ __forceinline__ void split2(float x, float y, uint32_t& hi, uint32_t& lo) {
    __nv_bfloat162 h = __floats2bfloat162_rn(x, y);
    hi = *(uint32_t*)&h;
    float rx = x - __bfloat162float(__low2bfloat16(h));
    float ry = y - __bfloat162float(__high2bfloat16(h));
    __nv_bfloat162 l = __floats2bfloat162_rn(rx, ry);
    lo = *(uint32_t*)&l;
}

// standard m16n8k16 bf16 mma, D/C fp32, A row-major frags, B col-major frags
__device__ __forceinline__ void mma_bf16(float* d, const uint32_t* a,
                                         uint32_t b0, uint32_t b1) {
    asm volatile(
        "mma.sync.aligned.m16n8k16.row.col.f32.bf16.bf16.f32 "
        "{%0,%1,%2,%3}, {%4,%5,%6,%7}, {%8,%9}, {%0,%1,%2,%3};"
        : "+f"(d[0]), "+f"(d[1]), "+f"(d[2]), "+f"(d[3])
        : "r"(a[0]), "r"(a[1]), "r"(a[2]), "r"(a[3]), "r"(b0), "r"(b1));
}

// fill B tiles (hi+lo) from prepacked bf16 weights: rows n=0..127, k-chunk kOff
__device__ __forceinline__ void fillB(uint32_t* sm, const __nv_bfloat16* bh,
                                      const __nv_bfloat16* bl, int strideElems,
                                      int kOff, int tid) {
#pragma unroll
    for (int i = 0; i < 32; i++) {
        int idx = tid + i * 256;
        int n = idx >> 6, w = idx & 63;
        sm[SB_H + n * WPAD + w] = *(const uint32_t*)(bh + (size_t)n * strideElems + kOff + 2 * w);
        sm[SB_L + n * WPAD + w] = *(const uint32_t*)(bl + (size_t)n * strideElems + kOff + 2 * w);
    }
}

// K=128 compute loop: warp computes 32 rows x 64 cols with 3-way bf16 split
__device__ __forceinline__ void kloop(const uint32_t* sm, int lane, int mbase,
                                      int nbase, float acc[2][8][4]) {
    const int g = lane >> 2, t = lane & 3;
#pragma unroll
    for (int ks = 0; ks < 8; ks++) {
        const int kw = ks * 8 + t;
        uint32_t ah[2][4], al[2][4];
#pragma unroll
        for (int mt = 0; mt < 2; mt++) {
            int r = mbase + mt * 16 + g;
            ah[mt][0] = sm[SA_H + r * WPAD + kw];
            ah[mt][1] = sm[SA_H + (r + 8) * WPAD + kw];
            ah[mt][2] = sm[SA_H + r * WPAD + kw + 4];
            ah[mt][3] = sm[SA_H + (r + 8) * WPAD + kw + 4];
            al[mt][0] = sm[SA_L + r * WPAD + kw];
            al[mt][1] = sm[SA_L + (r + 8) * WPAD + kw];
            al[mt][2] = sm[SA_L + r * WPAD + kw + 4];
            al[mt][3] = sm[SA_L + (r + 8) * WPAD + kw + 4];
        }
#pragma unroll
        for (int j = 0; j < 8; j++) {
            int n = nbase + j * 8 + g;
            uint32_t bh0 = sm[SB_H + n * WPAD + kw];
            uint32_t bh1 = sm[SB_H + n * WPAD + kw + 4];
            uint32_t bl0 = sm[SB_L + n * WPAD + kw];
            uint32_t bl1 = sm[SB_L + n * WPAD + kw + 4];
#pragma unroll
            for (int mt = 0; mt < 2; mt++) {
                mma_bf16(acc[mt][j], ah[mt], bh0, bh1);
                mma_bf16(acc[mt][j], ah[mt], bl0, bl1);
                mma_bf16(acc[mt][j], al[mt], bh0, bh1);
            }
        }
    }
}

// ---------------- small utility kernels --------------------------------------
__global__ void zero_kernel() {
    int stride = gridDim.x * blockDim.x;
    int t = blockIdx.x * blockDim.x + threadIdx.x;
    for (int i = t; i < NN * DD; i += stride) g_s[i] = 0.0f;
    for (int i = t; i < NN; i += stride) g_deg[i] = 0.0f;
}
__global__ void deg_kernel(const int* __restrict__ dst) {
    int e = blockIdx.x * blockDim.x + threadIdx.x;
    if (e < NE) atomicAdd(&g_deg[dst[e]], 1.0f);
}
__global__ void nb_kernel() {
    int stride = gridDim.x * blockDim.x;
    int t = blockIdx.x * blockDim.x + threadIdx.x;
    for (int i = t; i < NN * DD; i += stride) {
        float d = g_deg[i >> 7];
        g_s[i] = g_s[i] / fmaxf(d, 1.0f);
    }
}

// transpose + bf16-split weights. NOTE: destination __device__ globals are
// referenced DIRECTLY in device code — passing their symbols as host-side
// kernel arguments silently writes to the host shadow via ATS on GB300
// (that was the R3-R6 bug: zero weights => relu(bias) output).
__device__ __forceinline__ void split_one(const float* W, int K, int idx,
                                          __nv_bfloat16* Bh, __nv_bfloat16* Bl) {
    int n = idx / K, k = idx % K;
    float v = W[(size_t)k * 128 + n];
    __nv_bfloat16 h = __float2bfloat16(v);
    Bh[idx] = h;
    Bl[idx] = __float2bfloat16(v - __bfloat162float(h));
}
__global__ void split_w_node(const float* __restrict__ W) {
    int idx = blockIdx.x * blockDim.x + threadIdx.x;
    if (idx < 128 * 128) split_one(W, 128, idx, g_Bn_h, g_Bn_l);
}
__global__ void split_w_edge(const float* __restrict__ W) {
    int idx = blockIdx.x * blockDim.x + threadIdx.x;
    if (idx < 128 * 128) split_one(W, 128, idx, g_Be_h, g_Be_l);
}
__global__ void split_w_dense(const float* __restrict__ W) {
    int idx = blockIdx.x * blockDim.x + threadIdx.x;
    if (idx < 128 * 256) split_one(W, 256, idx, g_Bd_h, g_Bd_l);
}

// ---------------- GEMM kernels ------------------------------------------------

__global__ __launch_bounds__(256, 1)
void node_gemm(const float* __restrict__ nf, const float* __restrict__ bias,
               float* __restrict__ out) {
    extern __shared__ uint32_t sm[];
    const int tid = threadIdx.x, lane = tid & 31, wid = tid >> 5;
    const int rowbase = blockIdx.x * 128;

    fillB(sm, g_Bn_h, g_Bn_l, 128, 0, tid);
#pragma unroll
    for (int i = 0; i < 32; i++) {
        int idx = tid + i * 256;
        int r = idx >> 6, w = idx & 63;
        int row = rowbase + r;
        float2 v = make_float2(0.f, 0.f);
        if (row < NN) v = *(const float2*)(nf + (size_t)row * DD + 2 * w);
        split2(v.x, v.y, sm[SA_H + r * WPAD + w], sm[SA_L + r * WPAD + w]);
    }
    __syncthreads();

    const int mbase = (wid & 3) * 32, nbase = (wid >> 2) * 64;
    float acc[2][8][4];
#pragma unroll
    for (int a = 0; a < 2; a++)
#pragma unroll
        for (int b = 0; b < 8; b++)
#pragma unroll
            for (int c = 0; c < 4; c++) acc[a][b][c] = 0.f;
    kloop(sm, lane, mbase, nbase, acc);

    const int g = lane >> 2, t = lane & 3;
#pragma unroll
    for (int mt = 0; mt < 2; mt++) {
        int row = rowbase + mbase + mt * 16 + g;
#pragma unroll
        for (int j = 0; j < 8; j++) {
            int c = nbase + j * 8 + 2 * t;
            float2 bv = *(const float2*)(bias + c);
            if (row < NN) {
                float2 o = make_float2(fmaxf(acc[mt][j][0] + bv.x, 0.f),
                                       fmaxf(acc[mt][j][1] + bv.y, 0.f));
                *(float2*)(out + (size_t)row * DD + c) = o;
            }
            if (row + 8 < NN) {
                float2 o = make_float2(fmaxf(acc[mt][j][2] + bv.x, 0.f),
                                       fmaxf(acc[mt][j][3] + bv.y, 0.f));
                *(float2*)(out + (size_t)(row + 8) * DD + c) = o;
            }
        }
    }
}

__global__ __launch_bounds__(256, 1)
void edge_gemm(const float* __restrict__ ef, const int* __restrict__ dst) {
    extern __shared__ uint32_t sm[];
    const int tid = threadIdx.x, lane = tid & 31, wid = tid >> 5;
    const int e0 = blockIdx.x * 128;

    fillB(sm, g_Be_h, g_Be_l, 128, 0, tid);
#pragma unroll
    for (int i = 0; i < 32; i++) {
        int idx = tid + i * 256;
        int r = idx >> 6, w = idx & 63;
        float2 v = *(const float2*)(ef + (size_t)(e0 + r) * DD + 2 * w);
        split2(v.x, v.y, sm[SA_H + r * WPAD + w], sm[SA_L + r * WPAD + w]);
    }
    __syncthreads();

    const int mbase = (wid & 3) * 32, nbase = (wid >> 2) * 64;
    float acc[2][8][4];
#pragma unroll
    for (int a = 0; a < 2; a++)
#pragma unroll
        for (int b = 0; b < 8; b++)
#pragma unroll
            for (int c = 0; c < 4; c++) acc[a][b][c] = 0.f;
    kloop(sm, lane, mbase, nbase, acc);

    const int g = lane >> 2, t = lane & 3;
#pragma unroll
    for (int mt = 0; mt < 2; mt++) {
        int e = e0 + mbase + mt * 16 + g;
        int dn0 = dst[e], dn1 = dst[e + 8];
#pragma unroll
        for (int j = 0; j < 8; j++) {
            int c = nbase + j * 8 + 2 * t;
            float d0 = acc[mt][j][0], d1 = acc[mt][j][1];
            float d2 = acc[mt][j][2], d3 = acc[mt][j][3];
            *(float2*)(g_ef1 + (size_t)e * DD + c) = make_float2(d0, d1);
            *(float2*)(g_ef1 + (size_t)(e + 8) * DD + c) = make_float2(d2, d3);
            atomicAdd(g_s + (size_t)dn0 * DD + c, d0);
            atomicAdd(g_s + (size_t)dn0 * DD + c + 1, d1);
            atomicAdd(g_s + (size_t)dn1 * DD + c, d2);
            atomicAdd(g_s + (size_t)dn1 * DD + c + 1, d3);
        }
    }
}

__global__ __launch_bounds__(256, 1)
void edge_out_gemm(const int* __restrict__ src, const int* __restrict__ dst,
                   const float* __restrict__ db, const float* __restrict__ eb,
                   const float* __restrict__ nf2, float* __restrict__ out) {
    extern __shared__ uint32_t sm[];
    const int tid = threadIdx.x, lane = tid & 31, wid = tid >> 5;
    const int e0 = blockIdx.x * 128;
    const int mbase = (wid & 3) * 32, nbase = (wid >> 2) * 64;

    float acc[2][8][4];
#pragma unroll
    for (int a = 0; a < 2; a++)
#pragma unroll
        for (int b = 0; b < 8; b++)
#pragma unroll
            for (int c = 0; c < 4; c++) acc[a][b][c] = 0.f;

    // ---- phase 0: A = ef1 + nb[dst], B = dense rows [0:128) ----
    fillB(sm, g_Bd_h, g_Bd_l, KK, 0, tid);
#pragma unroll
    for (int i = 0; i < 32; i++) {
        int idx = tid + i * 256;
        int r = idx >> 6, w = idx & 63;
        int e = e0 + r;
        int dn = dst[e];
        float2 a = *(const float2*)(g_ef1 + (size_t)e * DD + 2 * w);
        float2 b = *(const float2*)(g_s + (size_t)dn * DD + 2 * w);
        split2(a.x + b.x, a.y + b.y, sm[SA_H + r * WPAD + w], sm[SA_L + r * WPAD + w]);
    }
    __syncthreads();
    kloop(sm, lane, mbase, nbase, acc);
    __syncthreads();

    // ---- phase 1: A = 0.5*(nf2[src]+nf2[dst]), B = dense rows [128:256) ----
    fillB(sm, g_Bd_h, g_Bd_l, KK, 128, tid);
#pragma unroll
    for (int i = 0; i < 32; i++) {
        int idx = tid + i * 256;
        int r = idx >> 6, w = idx & 63;
        int e = e0 + r;
        int sn = src[e], dn = dst[e];
        float2 a = *(const float2*)(nf2 + (size_t)sn * DD + 2 * w);
        float2 b = *(const float2*)(nf2 + (size_t)dn * DD + 2 * w);
        split2(0.5f * (a.x + b.x), 0.5f * (a.y + b.y),
               sm[SA_H + r * WPAD + w], sm[SA_L + r * WPAD + w]);
    }
    __syncthreads();
    kloop(sm, lane, mbase, nbase, acc);

    const int g = lane >> 2, t = lane & 3;
#pragma unroll
    for (int mt = 0; mt < 2; mt++) {
        int e = e0 + mbase + mt * 16 + g;
#pragma unroll
        for (int j = 0; j < 8; j++) {
            int c = nbase + j * 8 + 2 * t;
            float2 b1 = *(const float2*)(db + c);
            float2 b2 = *(const float2*)(eb + c);
            float2 o0 = make_float2(fmaxf(acc[mt][j][0] + b1.x + b2.x, 0.f),
                                    fmaxf(acc[mt][j][1] + b1.y + b2.y, 0.f));
            float2 o1 = make_float2(fmaxf(acc[mt][j][2] + b1.x + b2.x, 0.f),
                                    fmaxf(acc[mt][j][3] + b1.y + b2.y, 0.f));
            *(float2*)(out + (size_t)e * DD + c) = o0;
            *(float2*)(out + (size_t)(e + 8) * DD + c) = o1;
        }
    }
}

// ---------------- launch ------------------------------------------------------
extern "C" void kernel_launch(void* const* d_in, const int* in_sizes, int n_in,
                              void* d_out, int out_size) {
    (void)in_sizes; (void)n_in; (void)out_size;
    const float* nf        = (const float*)d_in[0];
    const float* ef        = (const float*)d_in[1];
    const float* W_node    = (const float*)d_in[2];
    const float* W_edge    = (const float*)d_in[3];
    const float* node_bias = (const float*)d_in[4];
    const float* edge_bias = (const float*)d_in[5];
    const float* dense_W   = (const float*)d_in[6];
    const float* dense_b   = (const float*)d_in[7];
    const int*   src       = (const int*)d_in[8];
    const int*   dst       = (const int*)d_in[9];

    float* nf2 = (float*)d_out;
    float* ef2 = (float*)d_out + (size_t)NN * DD;

    cudaFuncSetAttribute(node_gemm, cudaFuncAttributeMaxDynamicSharedMemorySize, SMEM_BYTES);
    cudaFuncSetAttribute(edge_gemm, cudaFuncAttributeMaxDynamicSharedMemorySize, SMEM_BYTES);
    cudaFuncSetAttribute(edge_out_gemm, cudaFuncAttributeMaxDynamicSharedMemorySize, SMEM_BYTES);

    zero_kernel<<<1024, 256>>>();
    deg_kernel<<<(NE + 255) / 256, 256>>>(dst);
    split_w_node<<<(128 * 128 + 255) / 256, 256>>>(W_node);
    split_w_edge<<<(128 * 128 + 255) / 256, 256>>>(W_edge);
    split_w_dense<<<(128 * 256 + 255) / 256, 256>>>(dense_W);

    node_gemm<<<(NN + 127) / 128, 256, SMEM_BYTES>>>(nf, node_bias, nf2);
    edge_gemm<<<NE / 128, 256, SMEM_BYTES>>>(ef, dst);
    nb_kernel<<<1024, 256>>>();
    edge_out_gemm<<<NE / 128, 256, SMEM_BYTES>>>(src, dst, dense_b, edge_bias, nf2, ef2);
}